// round 4
// baseline (speedup 1.0000x reference)
#include <cuda_runtime.h>

#define T_STEPS 4096
#define NCTA    128
#define NTHR    256

// ---------------- global scratch (static __device__ arrays; no allocs) ----------------
// h layout everywhere: [m4][b] float4  (m = m4*4 + comp), b = 0..63, m4 = 0..63
__device__ float4 g_h0buf[2][64][64];        // double-buffered h0 broadcast
__device__ float4 g_h1all[4098][64][64];     // h1 history, slot t+2 holds h1(t); slots 0,1 = zeros
__device__ float  g_yT[4099][64];            // yT[t+3][b] = y[b][t], rows 0..2 = -100 pad
__device__ unsigned g_count;
__device__ volatile unsigned g_sense;

// ---------------- helpers ----------------
__device__ __forceinline__ void cp16(unsigned dst, const void* src) {
    asm volatile("cp.async.cg.shared.global [%0], [%1], 16;\n" :: "r"(dst), "l"(src));
}
__device__ __forceinline__ void cp_commit() { asm volatile("cp.async.commit_group;\n"); }
template <int N> __device__ __forceinline__ void cp_wait() {
    asm volatile("cp.async.wait_group %0;\n" :: "n"(N));
}

__device__ __forceinline__ float sigf(float x)   { return 1.0f / (1.0f + __expf(-x)); }
__device__ __forceinline__ float tanh_f(float x) { return 2.0f * sigf(2.0f * x) - 1.0f; }

// ---------------- init: transpose/pad y, zero state, reset barrier ----------------
__global__ void init_kernel(const float* __restrict__ y) {
    int i = blockIdx.x * blockDim.x + threadIdx.x;
    const int NY = 4099 * 64;
    if (i < NY) {
        int row = i >> 6, b = i & 63;
        int t = row - 3;
        g_yT[row][b] = (t < 0) ? -100.0f : y[b * T_STEPS + t];
    }
    if (i < 2 * 64 * 64 * 4) ((float*)g_h0buf)[i] = 0.0f;   // both h0 slots
    if (i < 2 * 64 * 64 * 4) ((float*)g_h1all)[i] = 0.0f;   // h1 slots t=-2,-1
    if (i == 0) { g_count = 0u; g_sense = 0u; }
}

// ---------------- persistent 2-layer LSTM ----------------
// smem layout (floats):
//   hcat  [128][64] float4   @ 0       (32768)  rows 0..63: h0(p-1), 64..127: h1(p-2)
//   W0    [8][64]  float4    @ 32768   (2048)   W_hh0 slice
//   W1    [8][128] float4    @ 34816   (4096)   [W_ih1 | W_hh1] slice
//   wih0  [8][4]             @ 38912   (32)
//   b0s   [8]                @ 38944
//   b1s   [8]                @ 38952
//   g0b   [8][64]            @ 38960   (512)
//   g1b   [8][64]            @ 39472   (512)
//   c0s   [2][64]            @ 39984   (128)
//   c1s   [2][64]            @ 40112   (128)
//   yw    [4][64]            @ 40240   (256)
// total 40496 floats = 161984 bytes
#define SMEM_BYTES 161984

__global__ void __launch_bounds__(NTHR, 1) lstm_persist(
    const float* __restrict__ Wih0, const float* __restrict__ Whh0,
    const float* __restrict__ bih0, const float* __restrict__ bhh0,
    const float* __restrict__ Wih1, const float* __restrict__ Whh1,
    const float* __restrict__ bih1, const float* __restrict__ bhh1)
{
    extern __shared__ float sm[];
    float4* hcat = (float4*)sm;                  // [128*64]
    float4* W0   = (float4*)(sm + 32768);        // [8*64]
    float4* W1   = (float4*)(sm + 34816);        // [8*128]
    float*  wih0 = sm + 38912;
    float*  b0s  = sm + 38944;
    float*  b1s  = sm + 38952;
    float*  g0b  = sm + 38960;
    float*  g1b  = sm + 39472;
    float*  c0s  = sm + 39984;
    float*  c1s  = sm + 40112;
    float*  yw   = sm + 40240;

    const int tid = threadIdx.x;
    const int j0  = blockIdx.x * 2;      // this CTA owns hidden units j0, j0+1

    // load weight slices (local row lr = gate*2 + lj, global row = gate*256 + j0 + lj)
    for (int lr = 0; lr < 8; lr++) {
        int row = (lr >> 1) * 256 + j0 + (lr & 1);
        for (int m = tid; m < 256; m += NTHR) {
            ((float*)W0)[lr * 256 + m]       = Whh0[row * 256 + m];
            ((float*)W1)[lr * 512 + m]       = Wih1[row * 256 + m];
            ((float*)W1)[lr * 512 + 256 + m] = Whh1[row * 256 + m];
        }
    }
    if (tid < 8) {
        int row = (tid >> 1) * 256 + j0 + (tid & 1);
        b0s[tid] = bih0[row] + bhh0[row];
        b1s[tid] = bih1[row] + bhh1[row];
        for (int k = 0; k < 4; k++) wih0[tid * 4 + k] = Wih0[row * 4 + k];
    }
    if (tid < 128) { c0s[tid] = 0.0f; c1s[tid] = 0.0f; }
    __syncthreads();

    const unsigned hdst = (unsigned)__cvta_generic_to_shared(hcat);
    const int b   = tid & 63;
    const int rp  = tid >> 6;
    const int lr0 = rp * 2, lr1 = rp * 2 + 1;

    for (int p = 0; p <= T_STEPS; p++) {
        const float4* srcH0 = &g_h0buf[p & 1][0][0];
        const float4* srcH1 = &g_h1all[p][0][0];    // slot (p-2)+2 = p

        // async broadcast fetch: groups 0,1 = h0 (idx 0..4095), groups 2,3 = h1
        #pragma unroll
        for (int g = 0; g < 4; g++) {
            #pragma unroll
            for (int k = 0; k < 8; k++) {
                int idx = g * 2048 + k * 256 + tid;
                const float4* s = (g < 2) ? (srcH0 + idx) : (srcH1 + (idx - 4096));
                cp16(hdst + (unsigned)idx * 16u, s);
            }
            cp_commit();
        }
        if (p < T_STEPS) yw[tid] = g_yT[p + (tid >> 6)][b];
        __syncthreads();

        // ---- layer0: gates0 = x*Wih0^T + h0(p-1)*Whh0^T + b ----
        float a0 = 0.0f, a1 = 0.0f;
        if (p < T_STEPS) {
            a0 = b0s[lr0]; a1 = b0s[lr1];
            #pragma unroll
            for (int k = 0; k < 4; k++) {
                float xv = yw[k * 64 + b];
                a0 = fmaf(xv, wih0[lr0 * 4 + k], a0);
                a1 = fmaf(xv, wih0[lr1 * 4 + k], a1);
            }
        }
        cp_wait<3>(); __syncthreads();
        if (p < T_STEPS) {
            #pragma unroll 16
            for (int m4 = 0; m4 < 32; m4++) {
                float4 h  = hcat[m4 * 64 + b];
                float4 wA = W0[lr0 * 64 + m4];
                float4 wB = W0[lr1 * 64 + m4];
                a0 = fmaf(h.x, wA.x, a0); a0 = fmaf(h.y, wA.y, a0);
                a0 = fmaf(h.z, wA.z, a0); a0 = fmaf(h.w, wA.w, a0);
                a1 = fmaf(h.x, wB.x, a1); a1 = fmaf(h.y, wB.y, a1);
                a1 = fmaf(h.z, wB.z, a1); a1 = fmaf(h.w, wB.w, a1);
            }
        }
        cp_wait<2>(); __syncthreads();
        if (p < T_STEPS) {
            #pragma unroll 16
            for (int m4 = 32; m4 < 64; m4++) {
                float4 h  = hcat[m4 * 64 + b];
                float4 wA = W0[lr0 * 64 + m4];
                float4 wB = W0[lr1 * 64 + m4];
                a0 = fmaf(h.x, wA.x, a0); a0 = fmaf(h.y, wA.y, a0);
                a0 = fmaf(h.z, wA.z, a0); a0 = fmaf(h.w, wA.w, a0);
                a1 = fmaf(h.x, wB.x, a1); a1 = fmaf(h.y, wB.y, a1);
                a1 = fmaf(h.z, wB.z, a1); a1 = fmaf(h.w, wB.w, a1);
            }
            g0b[lr0 * 64 + b] = a0;
            g0b[lr1 * 64 + b] = a1;
        }
        cp_wait<0>(); __syncthreads();

        // ---- layer1: gates1 = [h0(p-1);h1(p-2)] * [Wih1|Whh1]^T + b ----
        if (p > 0) {
            float u0 = b1s[lr0], u1 = b1s[lr1];
            #pragma unroll 16
            for (int m4 = 0; m4 < 128; m4++) {
                float4 h  = hcat[m4 * 64 + b];
                float4 wA = W1[lr0 * 128 + m4];
                float4 wB = W1[lr1 * 128 + m4];
                u0 = fmaf(h.x, wA.x, u0); u0 = fmaf(h.y, wA.y, u0);
                u0 = fmaf(h.z, wA.z, u0); u0 = fmaf(h.w, wA.w, u0);
                u1 = fmaf(h.x, wB.x, u1); u1 = fmaf(h.y, wB.y, u1);
                u1 = fmaf(h.z, wB.z, u1); u1 = fmaf(h.w, wB.w, u1);
            }
            g1b[lr0 * 64 + b] = u0;
            g1b[lr1 * 64 + b] = u1;
        }
        __syncthreads();

        // ---- pointwise cell updates + publish h ----
        if (tid < 128) {
            int lj = tid >> 6;
            int j  = j0 + lj;
            if (p < T_STEPS) {
                float gi = g0b[(0 + lj) * 64 + b];
                float gf = g0b[(2 + lj) * 64 + b];
                float gg = g0b[(4 + lj) * 64 + b];
                float go = g0b[(6 + lj) * 64 + b];
                float c  = c0s[lj * 64 + b];
                c = sigf(gf) * c + sigf(gi) * tanh_f(gg);
                c0s[lj * 64 + b] = c;
                float h = sigf(go) * tanh_f(c);
                ((float*)&g_h0buf[(p + 1) & 1][j >> 2][b])[j & 3] = h;  // h0(p)
            }
            if (p > 0) {
                float gi = g1b[(0 + lj) * 64 + b];
                float gf = g1b[(2 + lj) * 64 + b];
                float gg = g1b[(4 + lj) * 64 + b];
                float go = g1b[(6 + lj) * 64 + b];
                float c  = c1s[lj * 64 + b];
                c = sigf(gf) * c + sigf(gi) * tanh_f(gg);
                c1s[lj * 64 + b] = c;
                float h = sigf(go) * tanh_f(c);
                ((float*)&g_h1all[p + 1][j >> 2][b])[j & 3] = h;        // h1(p-1) @ slot (p-1)+2
            }
        }
        __syncthreads();

        // ---- global barrier (sense-reversing, monotone counter) ----
        if (tid == 0) {
            __threadfence();
            unsigned target = (unsigned)(p + 1) * (unsigned)gridDim.x;
            unsigned a = atomicAdd(&g_count, 1u);
            if (a == target - 1u) {
                g_sense = target;
            } else {
                while (g_sense < target) { }
            }
            __threadfence();
        }
        __syncthreads();
    }
}

// ---------------- final projection: out[b][t][k] = h1(t) . W_out[k] + b_out[k] ----------------
__global__ void out_kernel(const float* __restrict__ Wout,
                           const float* __restrict__ bout,
                           float* __restrict__ out)
{
    __shared__ float w[2][256];
    __shared__ float bb[2];
    int t = blockIdx.x;
    int b = threadIdx.x;  // 64 threads
    for (int i = b; i < 512; i += 64) ((float*)w)[i] = Wout[i];
    if (b < 2) bb[b] = bout[b];
    __syncthreads();

    const float4* h = &g_h1all[t + 2][0][0];   // h1(t)
    float a0 = bb[0], a1 = bb[1];
    #pragma unroll 8
    for (int m4 = 0; m4 < 64; m4++) {
        float4 v = h[m4 * 64 + b];
        int m = m4 * 4;
        a0 += v.x * w[0][m] + v.y * w[0][m + 1] + v.z * w[0][m + 2] + v.w * w[0][m + 3];
        a1 += v.x * w[1][m] + v.y * w[1][m + 1] + v.z * w[1][m + 2] + v.w * w[1][m + 3];
    }
    out[b * (T_STEPS * 2) + t * 2 + 0] = a0;
    out[b * (T_STEPS * 2) + t * 2 + 1] = a1;
}

// ---------------- launcher ----------------
extern "C" void kernel_launch(void* const* d_in, const int* in_sizes, int n_in,
                              void* d_out, int out_size)
{
    (void)in_sizes; (void)n_in; (void)out_size;
    const float* y    = (const float*)d_in[0];
    const float* Wih0 = (const float*)d_in[1];
    const float* Whh0 = (const float*)d_in[2];
    const float* bih0 = (const float*)d_in[3];
    const float* bhh0 = (const float*)d_in[4];
    const float* Wih1 = (const float*)d_in[5];
    const float* Whh1 = (const float*)d_in[6];
    const float* bih1 = (const float*)d_in[7];
    const float* bhh1 = (const float*)d_in[8];
    const float* Wout = (const float*)d_in[9];
    const float* bout = (const float*)d_in[10];
    float* out = (float*)d_out;

    cudaFuncSetAttribute(lstm_persist, cudaFuncAttributeMaxDynamicSharedMemorySize, SMEM_BYTES);

    init_kernel<<<(4099 * 64 + 255) / 256, 256>>>(y);
    lstm_persist<<<NCTA, NTHR, SMEM_BYTES>>>(Wih0, Whh0, bih0, bhh0,
                                             Wih1, Whh1, bih1, bhh1);
    out_kernel<<<T_STEPS, 64>>>(Wout, bout, out);
}

// round 5
// speedup vs baseline: 1.4785x; 1.4785x over previous
#include <cuda_runtime.h>

#define T_STEPS 4096
#define NCTA    128
#define NTHR    256

typedef unsigned long long ull;

// ---------------- global scratch (static; no allocs) ----------------
// h layout: [m][b] floats (m = hidden unit 0..255, b = batch 0..63)
__device__ float g_h0[2][256][64];          // double-buffered h0 broadcast
__device__ float g_h1[4098][256][64];       // h1 history: slot t+2 = h1(t); slots 0,1 zero
__device__ float g_yT[4099][64];            // yT[t+3][b] = y[b][t]; rows 0..2 = -100 pad
__device__ unsigned g_count;
__device__ volatile unsigned g_sense;

// ---------------- helpers ----------------
__device__ __forceinline__ ull ffma2(ull h, ull w, ull a) {
    ull d;
    asm("fma.rn.f32x2 %0, %1, %2, %3;" : "=l"(d) : "l"(h), "l"(w), "l"(a));
    return d;
}
__device__ __forceinline__ ull pack2(float f) {
    unsigned u = __float_as_uint(f);
    return ((ull)u << 32) | (ull)u;
}
__device__ __forceinline__ float sigf(float x)   { return 1.0f / (1.0f + __expf(-x)); }
__device__ __forceinline__ float tanh_f(float x) { return 2.0f * sigf(2.0f * x) - 1.0f; }

// ---------------- init ----------------
__global__ void init_kernel(const float* __restrict__ y) {
    int i = blockIdx.x * blockDim.x + threadIdx.x;
    if (i < 4099 * 64) {
        int row = i >> 6, b = i & 63;
        int t = row - 3;
        g_yT[row][b] = (t < 0) ? -100.0f : y[b * T_STEPS + t];
    }
    if (i < 2 * 256 * 64) {           // both h0 buffers + h1 slots 0,1
        ((float*)g_h0)[i] = 0.0f;
        ((float*)g_h1)[i] = 0.0f;
    }
    if (i == 0) { g_count = 0u; g_sense = 0u; }
}

// ---------------- persistent 2-layer LSTM ----------------
// smem (ull-based):
//   W0d [8][256]  (w,w) pairs of W_hh0 slice      16384 B
//   W1d [8][512]  [Wih1 | Whh1] dup pairs         32768 B
//   P0  [8 q][8 r][32 b2] partial gate sums f32x2 16384 B
//   P1  same                                      16384 B
//   floats: wih0[32] b0s[8] b1s[8] c0s[128] c1s[128] yw[256]  = 2240 B
#define SMEM_BYTES (16384 + 32768 + 16384 + 16384 + 2240)

__global__ void __launch_bounds__(NTHR, 1) lstm_persist(
    const float* __restrict__ Wih0, const float* __restrict__ Whh0,
    const float* __restrict__ bih0, const float* __restrict__ bhh0,
    const float* __restrict__ Wih1, const float* __restrict__ Whh1,
    const float* __restrict__ bih1, const float* __restrict__ bhh1)
{
    extern __shared__ ull smu[];
    ull* W0d = smu;                    // [8][256]
    ull* W1d = W0d + 8 * 256;          // [8][512]
    ull* P0  = W1d + 8 * 512;          // [8][8][32]
    ull* P1  = P0 + 8 * 8 * 32;        // [8][8][32]
    float* fs   = (float*)(P1 + 8 * 8 * 32);
    float* wih0 = fs;                  // [8][4]
    float* b0s  = fs + 32;             // [8]
    float* b1s  = fs + 40;             // [8]
    float* c0s  = fs + 48;             // [2][64]
    float* c1s  = fs + 176;            // [2][64]
    float* yw   = fs + 304;            // [4][64]

    const int tid = threadIdx.x;
    const int j0  = blockIdx.x * 2;    // this CTA owns hidden units j0, j0+1

    // ---- load weight slices, duplicated (w,w) for f32x2 ----
    for (int idx = tid; idx < 8 * 256; idx += NTHR) {
        int r = idx >> 8, m = idx & 255;
        int row = (r >> 1) * 256 + j0 + (r & 1);   // r = gate*2 + lj
        W0d[idx]               = pack2(Whh0[row * 256 + m]);
        W1d[r * 512 + m]       = pack2(Wih1[row * 256 + m]);
        W1d[r * 512 + 256 + m] = pack2(Whh1[row * 256 + m]);
    }
    if (tid < 8) {
        int row = (tid >> 1) * 256 + j0 + (tid & 1);
        b0s[tid] = bih0[row] + bhh0[row];
        b1s[tid] = bih1[row] + bhh1[row];
        for (int k = 0; k < 4; k++) wih0[tid * 4 + k] = Wih0[row * 4 + k];
    }
    if (tid < 128) { c0s[tid] = 0.0f; c1s[tid] = 0.0f; }
    __syncthreads();

    const int b2 = tid & 31;           // batch pair index (b = 2*b2, 2*b2+1)
    const int q  = tid >> 5;           // m-chunk / warp id (0..7)
    const int hbase = q * 32 * 64 + 2 * b2;

    for (int p = 0; p <= T_STEPS; p++) {
        const float* H0 = &g_h0[p & 1][0][0];      // h0(p-1)
        const float* H1 = &g_h1[p][0][0];          // h1(p-2)

        // ---- fetch h chunks directly from L2 into registers ----
        ull h0r[32], h1r[32];
        #pragma unroll
        for (int m = 0; m < 32; m++)
            h0r[m] = __ldcg((const ull*)(H0 + hbase + m * 64));
        #pragma unroll
        for (int m = 0; m < 32; m++)
            h1r[m] = __ldcg((const ull*)(H1 + hbase + m * 64));
        if (p < T_STEPS) yw[tid] = g_yT[p + (tid >> 6)][tid & 63];

        // ---- layer0 partials: rows r=0..7, m-chunk [32q,32q+32) of h0 ----
        if (p < T_STEPS) {
            #pragma unroll
            for (int r = 0; r < 8; r++) {
                ull a = 0ull;
                const ull* Wp = W0d + r * 256 + q * 32;
                #pragma unroll
                for (int m2 = 0; m2 < 16; m2++) {
                    ulonglong2 w = *(const ulonglong2*)(Wp + 2 * m2);
                    a = ffma2(h0r[2 * m2],     w.x, a);
                    a = ffma2(h0r[2 * m2 + 1], w.y, a);
                }
                P0[(q * 8 + r) * 32 + b2] = a;
            }
        }

        // ---- layer1 partials: same h0 chunk (reg reuse) + h1 chunk ----
        if (p > 0) {
            #pragma unroll
            for (int r = 0; r < 8; r++) {
                ull a = 0ull;
                const ull* Wi = W1d + r * 512 + q * 32;
                const ull* Wh = W1d + r * 512 + 256 + q * 32;
                #pragma unroll
                for (int m2 = 0; m2 < 16; m2++) {
                    ulonglong2 w = *(const ulonglong2*)(Wi + 2 * m2);
                    a = ffma2(h0r[2 * m2],     w.x, a);
                    a = ffma2(h0r[2 * m2 + 1], w.y, a);
                }
                #pragma unroll
                for (int m2 = 0; m2 < 16; m2++) {
                    ulonglong2 w = *(const ulonglong2*)(Wh + 2 * m2);
                    a = ffma2(h1r[2 * m2],     w.x, a);
                    a = ffma2(h1r[2 * m2 + 1], w.y, a);
                }
                P1[(q * 8 + r) * 32 + b2] = a;
            }
        }
        __syncthreads();

        // ---- reduce partials, cell updates, publish h ----
        {
            const int lb   = tid & 63;
            const int lj   = (tid >> 6) & 1;
            const int half = tid >> 7;     // 0: layer0 cell, 1: layer1 cell
            const bool act = half ? (p > 0) : (p < T_STEPS);
            if (act) {
                const float* P = (const float*)(half ? P1 : P0);
                float g[4];
                #pragma unroll
                for (int gt = 0; gt < 4; gt++) {
                    int r = gt * 2 + lj;
                    float s = 0.0f;
                    #pragma unroll
                    for (int qq = 0; qq < 8; qq++)
                        s += P[(qq * 8 + r) * 64 + lb];
                    g[gt] = s;
                }
                if (half == 0) {
                    #pragma unroll
                    for (int gt = 0; gt < 4; gt++) {
                        int r = gt * 2 + lj;
                        float s = g[gt] + b0s[r];
                        #pragma unroll
                        for (int k = 0; k < 4; k++)
                            s = fmaf(yw[k * 64 + lb], wih0[r * 4 + k], s);
                        g[gt] = s;
                    }
                } else {
                    #pragma unroll
                    for (int gt = 0; gt < 4; gt++)
                        g[gt] += b1s[gt * 2 + lj];
                }
                float* cs = half ? c1s : c0s;
                float c = cs[lj * 64 + lb];
                c = sigf(g[1]) * c + sigf(g[0]) * tanh_f(g[2]);
                cs[lj * 64 + lb] = c;
                float h = sigf(g[3]) * tanh_f(c);
                int j = j0 + lj;
                if (half == 0) g_h0[(p + 1) & 1][j][lb] = h;   // h0(p)
                else           g_h1[p + 1][j][lb]       = h;   // h1(p-1)
            }
        }
        __syncthreads();

        // ---- global barrier (sense via monotone counter) ----
        if (tid == 0) {
            __threadfence();
            unsigned target = (unsigned)(p + 1) * (unsigned)gridDim.x;
            unsigned a = atomicAdd(&g_count, 1u);
            if (a == target - 1u) {
                g_sense = target;
            } else {
                while (g_sense < target) { }
            }
            __threadfence();
        }
        __syncthreads();
    }
}

// ---------------- final projection ----------------
__global__ void out_kernel(const float* __restrict__ Wout,
                           const float* __restrict__ bout,
                           float* __restrict__ out)
{
    __shared__ float w[512];
    __shared__ float bb[2];
    int t = blockIdx.x;
    int b = threadIdx.x;   // 64 threads
    for (int i = b; i < 512; i += 64) w[i] = Wout[i];
    if (b < 2) bb[b] = bout[b];
    __syncthreads();

    const float* h = &g_h1[t + 2][0][0];
    float a0 = bb[0], a1 = bb[1];
    #pragma unroll 8
    for (int m = 0; m < 256; m++) {
        float v = h[m * 64 + b];
        a0 = fmaf(v, w[m],       a0);
        a1 = fmaf(v, w[256 + m], a1);
    }
    out[b * (T_STEPS * 2) + t * 2 + 0] = a0;
    out[b * (T_STEPS * 2) + t * 2 + 1] = a1;
}

// ---------------- launcher ----------------
extern "C" void kernel_launch(void* const* d_in, const int* in_sizes, int n_in,
                              void* d_out, int out_size)
{
    (void)in_sizes; (void)n_in; (void)out_size;
    const float* y    = (const float*)d_in[0];
    const float* Wih0 = (const float*)d_in[1];
    const float* Whh0 = (const float*)d_in[2];
    const float* bih0 = (const float*)d_in[3];
    const float* bhh0 = (const float*)d_in[4];
    const float* Wih1 = (const float*)d_in[5];
    const float* Whh1 = (const float*)d_in[6];
    const float* bih1 = (const float*)d_in[7];
    const float* bhh1 = (const float*)d_in[8];
    const float* Wout = (const float*)d_in[9];
    const float* bout = (const float*)d_in[10];
    float* out = (float*)d_out;

    cudaFuncSetAttribute(lstm_persist, cudaFuncAttributeMaxDynamicSharedMemorySize, SMEM_BYTES);

    init_kernel<<<(4099 * 64 + 255) / 256, 256>>>(y);
    lstm_persist<<<NCTA, NTHR, SMEM_BYTES>>>(Wih0, Whh0, bih0, bhh0,
                                             Wih1, Whh1, bih1, bhh1);
    out_kernel<<<T_STEPS, 64>>>(Wout, bout, out);
}

// round 6
// speedup vs baseline: 1.5675x; 1.0602x over previous
#include <cuda_runtime.h>

#define T_STEPS 4096
#define NCTA    128
#define NTHR    256

typedef unsigned long long ull;

// ---------------- global scratch (static; no allocs) ----------------
// h layout: [m][b] floats (m = hidden unit 0..255, b = batch 0..63)
__device__ float g_h0[2][256][64];          // double-buffered h0 broadcast
__device__ float g_h1[4098][256][64];       // h1 history: slot t+2 = h1(t); slots 0,1 zero
__device__ float g_yT[4099][64];            // yT[t+3][b] = y[b][t]; rows 0..2 = -100 pad
__device__ unsigned g_count;

// ---------------- helpers ----------------
__device__ __forceinline__ ull ffma2(ull h, ull w, ull a) {
    ull d;
    asm("fma.rn.f32x2 %0, %1, %2, %3;" : "=l"(d) : "l"(h), "l"(w), "l"(a));
    return d;
}
__device__ __forceinline__ ull pack2(float f) {
    unsigned u = __float_as_uint(f);
    return ((ull)u << 32) | (ull)u;
}
__device__ __forceinline__ float sigf(float x)   { return 1.0f / (1.0f + __expf(-x)); }
__device__ __forceinline__ float tanh_f(float x) { return 2.0f * sigf(2.0f * x) - 1.0f; }

__device__ __forceinline__ void arrive_release(unsigned* p) {
    asm volatile("red.release.gpu.global.add.u32 [%0], 1;" :: "l"(p) : "memory");
}
__device__ __forceinline__ unsigned ld_acquire(const unsigned* p) {
    unsigned v;
    asm volatile("ld.acquire.gpu.global.u32 %0, [%1];" : "=r"(v) : "l"(p) : "memory");
    return v;
}

// ---------------- init ----------------
__global__ void init_kernel(const float* __restrict__ y) {
    int i = blockIdx.x * blockDim.x + threadIdx.x;
    if (i < 4099 * 64) {
        int row = i >> 6, b = i & 63;
        int t = row - 3;
        g_yT[row][b] = (t < 0) ? -100.0f : y[b * T_STEPS + t];
    }
    if (i < 2 * 256 * 64) {           // both h0 buffers + h1 slots 0,1
        ((float*)g_h0)[i] = 0.0f;
        ((float*)g_h1)[i] = 0.0f;
    }
    if (i == 0) g_count = 0u;
}

// ---------------- persistent 2-layer LSTM ----------------
// smem (ull-based):
//   W0d [8][256]  (w,w) pairs of W_hh0 slice      16384 B
//   W1d [8][512]  [Wih1 | Whh1] dup pairs         32768 B
//   P0  [8 q][8 r][32 b2] partial gate sums f32x2 16384 B
//   P1  same                                      16384 B
//   floats: wih0[32] b0s[8] b1s[8] c0s[128] c1s[128] yw[256]
#define SMEM_BYTES (16384 + 32768 + 16384 + 16384 + 2240)

__global__ void __launch_bounds__(NTHR, 1) lstm_persist(
    const float* __restrict__ Wih0, const float* __restrict__ Whh0,
    const float* __restrict__ bih0, const float* __restrict__ bhh0,
    const float* __restrict__ Wih1, const float* __restrict__ Whh1,
    const float* __restrict__ bih1, const float* __restrict__ bhh1)
{
    extern __shared__ ull smu[];
    ull* W0d = smu;                    // [8][256]
    ull* W1d = W0d + 8 * 256;          // [8][512]
    ull* P0  = W1d + 8 * 512;          // [8][8][32]
    ull* P1  = P0 + 8 * 8 * 32;        // [8][8][32]
    float* fs   = (float*)(P1 + 8 * 8 * 32);
    float* wih0 = fs;                  // [8][4]
    float* b0s  = fs + 32;             // [8]
    float* b1s  = fs + 40;             // [8]
    float* c0s  = fs + 48;             // [2][64]
    float* c1s  = fs + 176;            // [2][64]
    float* yw   = fs + 304;            // [4][64]

    const int tid = threadIdx.x;
    const int j0  = blockIdx.x * 2;    // this CTA owns hidden units j0, j0+1

    // ---- load weight slices, duplicated (w,w) for f32x2 ----
    for (int idx = tid; idx < 8 * 256; idx += NTHR) {
        int r = idx >> 8, m = idx & 255;
        int row = (r >> 1) * 256 + j0 + (r & 1);   // r = gate*2 + lj
        W0d[idx]               = pack2(Whh0[row * 256 + m]);
        W1d[r * 512 + m]       = pack2(Wih1[row * 256 + m]);
        W1d[r * 512 + 256 + m] = pack2(Whh1[row * 256 + m]);
    }
    if (tid < 8) {
        int row = (tid >> 1) * 256 + j0 + (tid & 1);
        b0s[tid] = bih0[row] + bhh0[row];
        b1s[tid] = bih1[row] + bhh1[row];
        for (int k = 0; k < 4; k++) wih0[tid * 4 + k] = Wih0[row * 4 + k];
    }
    if (tid < 128) { c0s[tid] = 0.0f; c1s[tid] = 0.0f; }
    __syncthreads();

    const int b2 = tid & 31;           // batch pair (b = 2*b2, 2*b2+1)
    const int q  = tid >> 5;           // m-chunk / warp id (0..7)
    const int hbase = q * 32 * 64 + 2 * b2;
    const ull* Wq0 = W0d + q * 32;               // + r*256 + m
    const ull* Wq1 = W1d + q * 32;               // + r*512 + m   (ih half)
    const ull* Wq1h = W1d + 256 + q * 32;        // + r*512 + m   (hh half)

    for (int p = 0; p <= T_STEPS; p++) {
        const float* B0 = &g_h0[p & 1][0][0] + hbase;   // h0(p-1) chunk base
        const float* B1 = &g_h1[p][0][0]     + hbase;   // h1(p-2) chunk base

        if (p < T_STEPS) yw[tid] = g_yT[p + (tid >> 6)][tid & 63];

        ull acc0[8], acc1[8];
        #pragma unroll
        for (int r = 0; r < 8; r++) { acc0[r] = 0ull; acc1[r] = 0ull; }

        // ---- streamed, double-buffered h chunks: 4x h0 then 4x h1 ----
        ull hb[2][8];
        #pragma unroll
        for (int k = 0; k < 8; k++)
            hb[0][k] = __ldcg((const ull*)(B0 + k * 64));

        #pragma unroll
        for (int c = 0; c < 8; c++) {
            const int cb = c & 1, nb = cb ^ 1;
            if (c < 7) {
                const float* nbase = (c + 1 < 4) ? (B0 + (c + 1) * 512)
                                                 : (B1 + (c - 3) * 512);
                #pragma unroll
                for (int k = 0; k < 8; k++)
                    hb[nb][k] = __ldcg((const ull*)(nbase + k * 64));
            }
            if (c < 4) {
                #pragma unroll
                for (int k2 = 0; k2 < 4; k2++) {
                    const int m2 = c * 8 + k2 * 2;
                    const ull hA = hb[cb][k2 * 2], hB = hb[cb][k2 * 2 + 1];
                    #pragma unroll
                    for (int r = 0; r < 8; r++) {
                        ulonglong2 w0 = *(const ulonglong2*)(Wq0 + r * 256 + m2);
                        acc0[r] = ffma2(hA, w0.x, acc0[r]);
                        acc0[r] = ffma2(hB, w0.y, acc0[r]);
                        ulonglong2 w1 = *(const ulonglong2*)(Wq1 + r * 512 + m2);
                        acc1[r] = ffma2(hA, w1.x, acc1[r]);
                        acc1[r] = ffma2(hB, w1.y, acc1[r]);
                    }
                }
            } else {
                #pragma unroll
                for (int k2 = 0; k2 < 4; k2++) {
                    const int m2 = (c - 4) * 8 + k2 * 2;
                    const ull hA = hb[cb][k2 * 2], hB = hb[cb][k2 * 2 + 1];
                    #pragma unroll
                    for (int r = 0; r < 8; r++) {
                        ulonglong2 w1 = *(const ulonglong2*)(Wq1h + r * 512 + m2);
                        acc1[r] = ffma2(hA, w1.x, acc1[r]);
                        acc1[r] = ffma2(hB, w1.y, acc1[r]);
                    }
                }
            }
        }
        #pragma unroll
        for (int r = 0; r < 8; r++) {
            P0[(q * 8 + r) * 32 + b2] = acc0[r];
            P1[(q * 8 + r) * 32 + b2] = acc1[r];
        }
        __syncthreads();

        // ---- reduce partials, cell updates, publish h ----
        {
            const int lb   = tid & 63;
            const int lj   = (tid >> 6) & 1;
            const int half = tid >> 7;     // 0: layer0 cell, 1: layer1 cell
            const bool act = half ? (p > 0) : (p < T_STEPS);
            if (act) {
                const float* P = (const float*)(half ? P1 : P0);
                float g[4];
                #pragma unroll
                for (int gt = 0; gt < 4; gt++) {
                    int r = gt * 2 + lj;
                    float s = 0.0f;
                    #pragma unroll
                    for (int qq = 0; qq < 8; qq++)
                        s += P[(qq * 8 + r) * 64 + lb];
                    g[gt] = s;
                }
                if (half == 0) {
                    #pragma unroll
                    for (int gt = 0; gt < 4; gt++) {
                        int r = gt * 2 + lj;
                        float s = g[gt] + b0s[r];
                        #pragma unroll
                        for (int k = 0; k < 4; k++)
                            s = fmaf(yw[k * 64 + lb], wih0[r * 4 + k], s);
                        g[gt] = s;
                    }
                } else {
                    #pragma unroll
                    for (int gt = 0; gt < 4; gt++)
                        g[gt] += b1s[gt * 2 + lj];
                }
                float* cs = half ? c1s : c0s;
                float c = cs[lj * 64 + lb];
                c = sigf(g[1]) * c + sigf(g[0]) * tanh_f(g[2]);
                cs[lj * 64 + lb] = c;
                float h = sigf(g[3]) * tanh_f(c);
                int j = j0 + lj;
                if (half == 0) g_h0[(p + 1) & 1][j][lb] = h;   // h0(p)
                else           g_h1[p + 1][j][lb]       = h;   // h1(p-1)
            }
        }
        __syncthreads();

        // ---- global barrier: release-add + acquire-poll on monotone counter ----
        if (tid == 0) {
            arrive_release(&g_count);
            const unsigned target = (unsigned)(p + 1) * (unsigned)NCTA;
            while (ld_acquire(&g_count) < target) { }
        }
        __syncthreads();
    }
}

// ---------------- final projection ----------------
__global__ void out_kernel(const float* __restrict__ Wout,
                           const float* __restrict__ bout,
                           float* __restrict__ out)
{
    __shared__ float w[512];
    __shared__ float bb[2];
    int t = blockIdx.x;
    int b = threadIdx.x;   // 64 threads
    for (int i = b; i < 512; i += 64) w[i] = Wout[i];
    if (b < 2) bb[b] = bout[b];
    __syncthreads();

    const float* h = &g_h1[t + 2][0][0];
    float a0 = bb[0], a1 = bb[1];
    #pragma unroll 8
    for (int m = 0; m < 256; m++) {
        float v = h[m * 64 + b];
        a0 = fmaf(v, w[m],       a0);
        a1 = fmaf(v, w[256 + m], a1);
    }
    out[b * (T_STEPS * 2) + t * 2 + 0] = a0;
    out[b * (T_STEPS * 2) + t * 2 + 1] = a1;
}

// ---------------- launcher ----------------
extern "C" void kernel_launch(void* const* d_in, const int* in_sizes, int n_in,
                              void* d_out, int out_size)
{
    (void)in_sizes; (void)n_in; (void)out_size;
    const float* y    = (const float*)d_in[0];
    const float* Wih0 = (const float*)d_in[1];
    const float* Whh0 = (const float*)d_in[2];
    const float* bih0 = (const float*)d_in[3];
    const float* bhh0 = (const float*)d_in[4];
    const float* Wih1 = (const float*)d_in[5];
    const float* Whh1 = (const float*)d_in[6];
    const float* bih1 = (const float*)d_in[7];
    const float* bhh1 = (const float*)d_in[8];
    const float* Wout = (const float*)d_in[9];
    const float* bout = (const float*)d_in[10];
    float* out = (float*)d_out;

    cudaFuncSetAttribute(lstm_persist, cudaFuncAttributeMaxDynamicSharedMemorySize, SMEM_BYTES);

    init_kernel<<<(4099 * 64 + 255) / 256, 256>>>(y);
    lstm_persist<<<NCTA, NTHR, SMEM_BYTES>>>(Wih0, Whh0, bih0, bhh0,
                                             Wih1, Whh1, bih1, bhh1);
    out_kernel<<<T_STEPS, 64>>>(Wout, bout, out);
}

// round 7
// speedup vs baseline: 1.7344x; 1.1065x over previous
#include <cuda_runtime.h>

#define T_STEPS 4096
#define NCTA    128
#define NTHR    256

typedef unsigned long long ull;

// ---------------- global scratch (static; no allocs) ----------------
// h layout: [m][b] floats (m = hidden unit 0..255, b = batch 0..63)
__device__ __align__(256) float g_h0[2][256][64];     // double-buffered h0 broadcast
__device__ __align__(256) float g_h1[4098][256][64];  // h1 history: slot t+2 = h1(t)
__device__ __align__(256) float g_yT[4099][64];       // yT[t+3][b] = y[b][t]; rows 0..2 pad
__device__ unsigned g_cnt;    // zero-init at load; invariant: 0 between runs
__device__ unsigned g_sense;  // zero-init; invariant: 0 between runs (even round count)

// ---------------- helpers ----------------
__device__ __forceinline__ ull ffma2(ull h, ull w, ull a) {
    ull d;
    asm("fma.rn.f32x2 %0, %1, %2, %3;" : "=l"(d) : "l"(h), "l"(w), "l"(a));
    return d;
}
__device__ __forceinline__ ull pack2(float f) {
    unsigned u = __float_as_uint(f);
    return ((ull)u << 32) | (ull)u;
}
__device__ __forceinline__ float sigf(float x)   { return 1.0f / (1.0f + __expf(-x)); }
__device__ __forceinline__ float tanh_f(float x) { return 2.0f * sigf(2.0f * x) - 1.0f; }

__device__ __forceinline__ ulonglong2 ldcg2(const float* p) {
    ulonglong2 v;
    asm volatile("ld.global.cg.v2.u64 {%0,%1}, [%2];" : "=l"(v.x), "=l"(v.y) : "l"(p));
    return v;
}
__device__ __forceinline__ unsigned atom_add_acqrel(unsigned* p, unsigned v) {
    unsigned old;
    asm volatile("atom.acq_rel.gpu.global.add.u32 %0, [%1], %2;"
                 : "=r"(old) : "l"(p), "r"(v) : "memory");
    return old;
}
__device__ __forceinline__ unsigned ld_acquire(const unsigned* p) {
    unsigned v;
    asm volatile("ld.acquire.gpu.global.u32 %0, [%1];" : "=r"(v) : "l"(p) : "memory");
    return v;
}
__device__ __forceinline__ void st_release(unsigned* p, unsigned v) {
    asm volatile("st.release.gpu.global.u32 [%0], %1;" :: "l"(p), "r"(v) : "memory");
}
__device__ __forceinline__ void st_relaxed(unsigned* p, unsigned v) {
    asm volatile("st.relaxed.gpu.global.u32 [%0], %1;" :: "l"(p), "r"(v) : "memory");
}

// self-resetting sense-reversing grid barrier (all NCTA CTAs resident)
__device__ __forceinline__ void grid_barrier(int tid, unsigned& ls) {
    __syncthreads();
    if (tid == 0) {
        ls ^= 1u;
        unsigned old = atom_add_acqrel(&g_cnt, 1u);
        if (old == NCTA - 1u) {
            st_relaxed(&g_cnt, 0u);
            st_release(&g_sense, ls);
        } else {
            while (ld_acquire(&g_sense) != ls) { }
        }
    }
    __syncthreads();
}

// ---------------- the whole problem in one kernel ----------------
// smem layout (bytes):
//   W0v  ulonglong2[1024]  @ 0       16384   W_hh0 dup-pairs, half-warp interleaved
//   W1v  ulonglong2[1024]  @ 16384   16384   W_ih1 (h0 operand)
//   WHv  ulonglong2[1024]  @ 32768   16384   W_hh1 (h1 operand)
//   P0   ulonglong2[2048]  @ 49152   32768   layer0 partials [16q][8r][16g]{lo,hi}
//   P1   ulonglong2[2048]  @ 81920   32768
//   floats @ 114688: wih0[32] b0s[8] b1s[8] c0s[128] c1s[128] yw[256] wout[512] bo2[2]
#define SMEM_BYTES (114688 + 4296)

__global__ void __launch_bounds__(NTHR, 1) lstm_all(
    const float* __restrict__ y,
    const float* __restrict__ Wih0, const float* __restrict__ Whh0,
    const float* __restrict__ bih0, const float* __restrict__ bhh0,
    const float* __restrict__ Wih1, const float* __restrict__ Whh1,
    const float* __restrict__ bih1, const float* __restrict__ bhh1,
    const float* __restrict__ Wout, const float* __restrict__ bout,
    float* __restrict__ out)
{
    extern __shared__ char smraw[];
    ulonglong2* W0v = (ulonglong2*)smraw;
    ulonglong2* W1v = (ulonglong2*)(smraw + 16384);
    ulonglong2* WHv = (ulonglong2*)(smraw + 32768);
    ulonglong2* P0v = (ulonglong2*)(smraw + 49152);
    ulonglong2* P1v = (ulonglong2*)(smraw + 81920);
    float* fs   = (float*)(smraw + 114688);
    float* wih0 = fs;            // [8][4]
    float* b0s  = fs + 32;       // [8]
    float* b1s  = fs + 40;       // [8]
    float* c0s  = fs + 48;       // [2][64]
    float* c1s  = fs + 176;      // [2][64]
    float* yw   = fs + 304;      // [4][64]
    float* wout = fs + 560;      // [2][256]
    float* bo2  = fs + 1072;     // [2]

    const int tid = threadIdx.x;
    const int bid = blockIdx.x;
    const int j0  = bid * 2;                 // CTA owns hidden units j0, j0+1
    unsigned ls = 0;

    // ======== init: global state ========
    {
        int gi = bid * NTHR + tid;           // 0..32767
        if (gi < 16384) {                    // zero h0 (both) + h1 slots 0,1
            ((float*)g_h0)[gi]         = 0.0f;
            ((float*)g_h0)[16384 + gi] = 0.0f;
            ((float*)g_h1)[gi]         = 0.0f;
            ((float*)g_h1)[16384 + gi] = 0.0f;
        }
        for (int i = gi; i < 4099 * 64; i += NCTA * NTHR) {
            int row = i >> 6, b = i & 63;
            g_yT[row][b] = (row < 3) ? -100.0f : y[b * T_STEPS + (row - 3)];
        }
    }

    // ======== init: smem weights (interleaved half-warp layout) ========
    // flat ull index u = w*256 + r*32 + i*4 + hf*2 + j
    {
        ull* W0u = (ull*)W0v; ull* W1u = (ull*)W1v; ull* WHu = (ull*)WHv;
        for (int u = tid; u < 2048; u += NTHR) {
            int j  = u & 1;
            int hf = (u >> 1) & 1;
            int i  = (u >> 2) & 7;
            int r  = (u >> 5) & 7;
            int w  = (u >> 8) & 7;
            int m   = (w * 2 + hf) * 16 + 2 * i + j;
            int row = (r >> 1) * 256 + j0 + (r & 1);
            W0u[u] = pack2(Whh0[row * 256 + m]);
            W1u[u] = pack2(Wih1[row * 256 + m]);
            WHu[u] = pack2(Whh1[row * 256 + m]);
        }
        if (tid < 8) {
            int row = (tid >> 1) * 256 + j0 + (tid & 1);
            b0s[tid] = bih0[row] + bhh0[row];
            b1s[tid] = bih1[row] + bhh1[row];
            for (int k = 0; k < 4; k++) wih0[tid * 4 + k] = Wih0[row * 4 + k];
        }
        if (tid < 128) { c0s[tid] = 0.0f; c1s[tid] = 0.0f; }
        for (int i = tid; i < 512; i += NTHR) wout[i] = Wout[i];
        if (tid < 2) bo2[tid] = bout[tid];
    }
    grid_barrier(tid, ls);   // round 1

    // ======== persistent 2-layer LSTM ========
    const int w    = tid >> 5;
    const int lane = tid & 31;
    const int hf   = lane >> 4;          // half-warp
    const int g    = lane & 15;          // bp-group -> batches 4g..4g+3
    const int q    = w * 2 + hf;         // 16 m-chunks of 16
    const int wb   = w * 128 + hf;       // ull2 weight base: + r*16 + i*2
    const int hoff = q * 16 * 64 + 4 * g;

    for (int p = 0; p <= T_STEPS; p++) {
        const float* H0 = &g_h0[p & 1][0][0] + hoff;   // h0(p-1) slice
        const float* H1 = &g_h1[p][0][0]     + hoff;   // h1(p-2) slice
        if (p < T_STEPS) yw[tid] = g_yT[p + (tid >> 6)][tid & 63];

        ull a0lo[8], a0hi[8], a1lo[8], a1hi[8];
        #pragma unroll
        for (int r = 0; r < 8; r++) { a0lo[r]=0; a0hi[r]=0; a1lo[r]=0; a1hi[r]=0; }

        ulonglong2 hb[2][8];
        #pragma unroll
        for (int k = 0; k < 8; k++) hb[0][k] = ldcg2(H0 + k * 64);

        #pragma unroll
        for (int c = 0; c < 4; c++) {
            const int cb = c & 1;
            if (c < 3) {
                const float* nb = (c == 0) ? (H0 + 8 * 64) : (H1 + (c - 1) * 8 * 64);
                #pragma unroll
                for (int k = 0; k < 8; k++) hb[cb ^ 1][k] = ldcg2(nb + k * 64);
            }
            if (c < 2) {
                #pragma unroll
                for (int i2 = 0; i2 < 4; i2++) {
                    const int i = c * 4 + i2;
                    const ulonglong2 hA = hb[cb][2 * i2], hB = hb[cb][2 * i2 + 1];
                    #pragma unroll
                    for (int r = 0; r < 8; r++) {
                        ulonglong2 w0 = W0v[wb + r * 16 + i * 2];
                        a0lo[r] = ffma2(hA.x, w0.x, a0lo[r]);
                        a0hi[r] = ffma2(hA.y, w0.x, a0hi[r]);
                        a0lo[r] = ffma2(hB.x, w0.y, a0lo[r]);
                        a0hi[r] = ffma2(hB.y, w0.y, a0hi[r]);
                        ulonglong2 w1 = W1v[wb + r * 16 + i * 2];
                        a1lo[r] = ffma2(hA.x, w1.x, a1lo[r]);
                        a1hi[r] = ffma2(hA.y, w1.x, a1hi[r]);
                        a1lo[r] = ffma2(hB.x, w1.y, a1lo[r]);
                        a1hi[r] = ffma2(hB.y, w1.y, a1hi[r]);
                    }
                }
            } else {
                #pragma unroll
                for (int i2 = 0; i2 < 4; i2++) {
                    const int i = (c - 2) * 4 + i2;
                    const ulonglong2 hA = hb[cb][2 * i2], hB = hb[cb][2 * i2 + 1];
                    #pragma unroll
                    for (int r = 0; r < 8; r++) {
                        ulonglong2 wh = WHv[wb + r * 16 + i * 2];
                        a1lo[r] = ffma2(hA.x, wh.x, a1lo[r]);
                        a1hi[r] = ffma2(hA.y, wh.x, a1hi[r]);
                        a1lo[r] = ffma2(hB.x, wh.y, a1lo[r]);
                        a1hi[r] = ffma2(hB.y, wh.y, a1hi[r]);
                    }
                }
            }
        }
        #pragma unroll
        for (int r = 0; r < 8; r++) {
            P0v[(q * 8 + r) * 16 + g] = make_ulonglong2(a0lo[r], a0hi[r]);
            P1v[(q * 8 + r) * 16 + g] = make_ulonglong2(a1lo[r], a1hi[r]);
        }
        __syncthreads();

        // ---- reduce 16 partials, cell update, publish h ----
        {
            const int lb    = tid & 63;
            const int lj    = (tid >> 6) & 1;
            const int half2 = tid >> 7;     // 0: layer0 cell, 1: layer1 cell
            const bool act  = half2 ? (p > 0) : (p < T_STEPS);
            if (act) {
                const float* P = (const float*)(half2 ? P1v : P0v);
                float gg[4];
                #pragma unroll
                for (int gt = 0; gt < 4; gt++) {
                    int r = gt * 2 + lj;
                    float s = 0.0f;
                    #pragma unroll
                    for (int qq = 0; qq < 16; qq++)
                        s += P[(qq * 8 + r) * 64 + lb];
                    gg[gt] = s;
                }
                if (half2 == 0) {
                    #pragma unroll
                    for (int gt = 0; gt < 4; gt++) {
                        int r = gt * 2 + lj;
                        float s = gg[gt] + b0s[r];
                        #pragma unroll
                        for (int k = 0; k < 4; k++)
                            s = fmaf(yw[k * 64 + lb], wih0[r * 4 + k], s);
                        gg[gt] = s;
                    }
                } else {
                    #pragma unroll
                    for (int gt = 0; gt < 4; gt++)
                        gg[gt] += b1s[gt * 2 + lj];
                }
                float* cs = half2 ? c1s : c0s;
                float c = cs[lj * 64 + lb];
                c = sigf(gg[1]) * c + sigf(gg[0]) * tanh_f(gg[2]);
                cs[lj * 64 + lb] = c;
                float h = sigf(gg[3]) * tanh_f(c);
                int j = j0 + lj;
                if (half2 == 0) g_h0[(p + 1) & 1][j][lb] = h;   // h0(p)
                else            g_h1[p + 1][j][lb]       = h;   // h1(p-1)
            }
        }
        grid_barrier(tid, ls);   // rounds 2..4098 (total even)
    }

    // ======== output projection: out[b][t][k] = h1(t).Wout[k] + bout[k] ========
    {
        const int b  = tid & 63;
        const int tt = tid >> 6;    // 0..3
        for (int t5 = 0; t5 < 8; t5++) {
            int t = bid * 32 + tt * 8 + t5;
            const float* h = &g_h1[t + 2][0][0];
            float s0 = bo2[0], s1 = bo2[1];
            #pragma unroll 8
            for (int m = 0; m < 256; m++) {
                float v = h[m * 64 + b];
                s0 = fmaf(v, wout[m],       s0);
                s1 = fmaf(v, wout[256 + m], s1);
            }
            out[b * (T_STEPS * 2) + t * 2 + 0] = s0;
            out[b * (T_STEPS * 2) + t * 2 + 1] = s1;
        }
    }
}

// ---------------- launcher: ONE kernel ----------------
extern "C" void kernel_launch(void* const* d_in, const int* in_sizes, int n_in,
                              void* d_out, int out_size)
{
    (void)in_sizes; (void)n_in; (void)out_size;
    cudaFuncSetAttribute(lstm_all, cudaFuncAttributeMaxDynamicSharedMemorySize, SMEM_BYTES);
    lstm_all<<<NCTA, NTHR, SMEM_BYTES>>>(
        (const float*)d_in[0],
        (const float*)d_in[1], (const float*)d_in[2],
        (const float*)d_in[3], (const float*)d_in[4],
        (const float*)d_in[5], (const float*)d_in[6],
        (const float*)d_in[7], (const float*)d_in[8],
        (const float*)d_in[9], (const float*)d_in[10],
        (float*)d_out);
}